// round 13
// baseline (speedup 1.0000x reference)
#include <cuda_runtime.h>
#include <cuda_fp16.h>
#include <cstdint>

#define NN 4096
#define DD 512
#define BM 128
#define BN 128
#define KC 64                    // fp16 K elems per chunk = 128B per row
#define NCHUNK (DD / KC)         // 8
#define NTILES ((NN / BM) * (NN / BN))   // 1024
#define MARGIN_F 0.3f

#define TILE_BYTES (BM * 128)    // 16 KB per operand per stage
#define A_OFF(s) ((s) * TILE_BYTES)
#define B_OFF(s) (2 * TILE_BYTES + (s) * TILE_BYTES)
#define DYN_SMEM (4 * TILE_BYTES)   // 64 KB (2-stage double buffer)

__device__ float    g_e1[NN];
__device__ float    g_e2[NN];
__device__ unsigned g_ap[NN];      // non-negative float bits, atomicMax
__device__ unsigned g_an[NN];      // non-negative float bits, atomicMin
__device__ int      g_lab[NN];
__device__ __half   g_srch[NN * DD];   // fp16 copies (4 MB each)
__device__ __half   g_tgth[NN * DD];
__device__ unsigned g_tick;            // persistent-CTA tile ticket

// ---------------------------------------------------------------------------
__device__ __forceinline__ uint32_t h2_bits(__half2 h) {
    return *reinterpret_cast<uint32_t*>(&h);
}
__device__ __forceinline__ uint32_t smem_u32(const void* p) {
    uint32_t a;
    asm("{ .reg .u64 t; cvta.to.shared.u64 t, %1; cvt.u32.u64 %0, t; }"
        : "=r"(a) : "l"(p));
    return a;
}
__device__ __forceinline__ void cp_async16(uint32_t dst, const void* src) {
    asm volatile("cp.async.cg.shared.global [%0], [%1], 16;" :: "r"(dst), "l"(src));
}
__device__ __forceinline__ void ldsm_x4(uint32_t addr, uint32_t& r0, uint32_t& r1,
                                        uint32_t& r2, uint32_t& r3) {
    asm volatile("ldmatrix.sync.aligned.m8n8.x4.shared.b16 {%0,%1,%2,%3}, [%4];"
                 : "=r"(r0), "=r"(r1), "=r"(r2), "=r"(r3) : "r"(addr));
}
__device__ __forceinline__ void mma_f16(float* d, uint32_t a0, uint32_t a1,
                                        uint32_t a2, uint32_t a3,
                                        uint32_t b0, uint32_t b1) {
    asm volatile(
        "mma.sync.aligned.m16n8k16.row.col.f32.f16.f16.f32 "
        "{%0,%1,%2,%3}, {%4,%5,%6,%7}, {%8,%9}, {%0,%1,%2,%3};"
        : "+f"(d[0]), "+f"(d[1]), "+f"(d[2]), "+f"(d[3])
        : "r"(a0), "r"(a1), "r"(a2), "r"(a3), "r"(b0), "r"(b1));
}

// ---------------------------------------------------------------------------
// prep: warp-per-(row, array) fp32->fp16 convert + norms + accumulator init.
// Block 0 additionally: label dtype detect + normalize, ticket reset.
// ---------------------------------------------------------------------------
__global__ void __launch_bounds__(256) prep_kernel(const float* __restrict__ src,
                                                   const float* __restrict__ tgt,
                                                   const int* __restrict__ lab32) {
    const int wid = threadIdx.x >> 5;
    const int lid = threadIdx.x & 31;
    const int slot = blockIdx.x * 8 + wid;
    const int row = slot >> 1;
    const int arr = slot & 1;

    const float* base = arr ? tgt : src;
    __half* dsth = arr ? g_tgth : g_srch;

    const float4* s4 = (const float4*)(base + (size_t)row * DD);
    uint2* oh = (uint2*)(dsth + (size_t)row * DD);

    float4 xs[4];
#pragma unroll
    for (int i = 0; i < 4; i++) xs[i] = s4[lid + 32 * i];

    float a = 0.f;
#pragma unroll
    for (int i = 0; i < 4; i++) {
        float4 x = xs[i];
        a = fmaf(x.x, x.x, a); a = fmaf(x.y, x.y, a);
        a = fmaf(x.z, x.z, a); a = fmaf(x.w, x.w, a);
        uint2 o;
        o.x = h2_bits(__floats2half2_rn(x.x, x.y));
        o.y = h2_bits(__floats2half2_rn(x.z, x.w));
        oh[lid + 32 * i] = o;
    }
#pragma unroll
    for (int o = 16; o > 0; o >>= 1)
        a += __shfl_xor_sync(0xffffffffu, a, o);
    if (lid == 0) {
        if (arr == 0) {
            g_e1[row] = a;
            g_ap[row] = 0u;
            g_an[row] = 0x7f800000u;
        } else {
            g_e2[row] = a;
        }
    }

    if (blockIdx.x == 0) {
        __shared__ int any_odd_nonzero;
        const int t = threadIdx.x;
        if (t == 0) { any_odd_nonzero = 0; g_tick = 0u; }
        __syncthreads();
        int local = 0;
        for (int i = 2 * t + 1; i < NN; i += 2 * 256)
            if (lab32[i] != 0) local = 1;
        if (local) atomicOr(&any_odd_nonzero, 1);
        __syncthreads();
        bool is64 = (any_odd_nonzero == 0);
        for (int i = t; i < NN; i += 256)
            g_lab[i] = is64 ? lab32[2 * i] : lab32[i];
    }
}

// ---------------------------------------------------------------------------
// dist_mma: PERSISTENT CTAs (dynamic ticket), cross-tile software pipeline.
// Per-chunk structure identical to best measured (R7): fill next, commit,
// wait 1, sync, compute, sync. At c==7 the "next" fill is the NEXT TILE's
// chunk 0 (ticket grabbed at c==5, published by c==6's barriers); next
// tile's chunk 1 is filled during the epilogue.
// 8 warps: 4 (M) x 2 (N); warp tile 32x64.
// ---------------------------------------------------------------------------
__global__ void __launch_bounds__(256, 2) dist_mma_kernel() {
    extern __shared__ char smem[];
    __shared__ float sE1[BM], sE2[BN];
    __shared__ int   sLr[BM], sLc[BN];
    __shared__ unsigned sAp[BM], sAn[BM];
    __shared__ int s_tick;

    const int tid = threadIdx.x;
    const int wid = tid >> 5;
    const int lid = tid & 31;
    const int gid = lid >> 2;
    const int t4  = lid & 3;
    const int warpM = wid & 3;
    const int warpN = wid >> 2;

    const uint32_t sbase = smem_u32(smem);
    const int l7 = lid & 7;
    uint32_t aRow[2];
#pragma unroll
    for (int mf = 0; mf < 2; mf++)
        aRow[mf] = (uint32_t)((warpM * 32 + mf * 16 + ((lid >> 3) & 1) * 8 + l7) * 128);
    const int aSel = lid >> 4;
    uint32_t bCol[4];
#pragma unroll
    for (int p = 0; p < 4; p++)
        bCol[p] = (uint32_t)((warpN * 64 + p * 16 + (lid >> 4) * 8 + l7) * 128);
    const int bSel = (lid >> 3) & 1;

    auto load_chunk = [&](const __half* __restrict__ base, int rb, int kt, uint32_t dst) {
#pragma unroll
        for (int i = 0; i < 4; i++) {
            int f = tid + i * 256;
            int r = f >> 3;
            int c16 = f & 7;
            const __half* g = base + (size_t)(rb + r) * DD + kt + c16 * 8;
            cp_async16(dst + r * 128 + ((c16 ^ (r & 7)) << 4), g);
        }
    };

    // ---- first ticket ----
    if (tid == 0) s_tick = (int)atomicAdd(&g_tick, 1u);
    __syncthreads();
    int t = s_tick;
    if (t >= NTILES) return;
    int rowBase = (t >> 5) * BM;
    int colBase = (t & 31) * BN;

    if (tid < 128) {
        sAp[tid] = 0u;
        sAn[tid] = 0x7f800000u;
        sE1[tid] = g_e1[rowBase + tid];
        sE2[tid] = g_e2[colBase + tid];
        sLr[tid] = g_lab[rowBase + tid];
        sLc[tid] = g_lab[colBase + tid];
    }

    float acc[2][8][4];
#pragma unroll
    for (int mf = 0; mf < 2; mf++)
#pragma unroll
        for (int nf = 0; nf < 8; nf++)
#pragma unroll
            for (int v = 0; v < 4; v++) acc[mf][nf][v] = 0.f;

    // prologue: this tile's chunk 0
    load_chunk(g_srch, rowBase, 0, sbase + A_OFF(0));
    load_chunk(g_tgth, colBase, 0, sbase + B_OFF(0));
    asm volatile("cp.async.commit_group;");

    int t_next = NTILES;

    for (;;) {
        for (int c = 0; c < NCHUNK; c++) {
            if (c + 1 < NCHUNK) {
                int sn = (c + 1) & 1;
                load_chunk(g_srch, rowBase, (c + 1) * KC, sbase + A_OFF(sn));
                load_chunk(g_tgth, colBase, (c + 1) * KC, sbase + B_OFF(sn));
            } else {
                t_next = s_tick;   // published by c==6's barriers
                if (t_next < NTILES) {
                    int rb = (t_next >> 5) * BM;
                    int cb = (t_next & 31) * BN;
                    load_chunk(g_srch, rb, 0, sbase + A_OFF(0));
                    load_chunk(g_tgth, cb, 0, sbase + B_OFF(0));
                }
            }
            asm volatile("cp.async.commit_group;");
            asm volatile("cp.async.wait_group 1;");   // chunk c's group complete
            __syncthreads();
            if (c == 5 && tid == 0) s_tick = (int)atomicAdd(&g_tick, 1u);

            const uint32_t Ab = sbase + A_OFF(c & 1);
            const uint32_t Bb = sbase + B_OFF(c & 1);
#pragma unroll
            for (int s = 0; s < 4; s++) {          // 4 x K=16
                uint32_t a[2][4];
#pragma unroll
                for (int mf = 0; mf < 2; mf++) {
                    uint32_t addr = Ab + aRow[mf] + ((uint32_t)((s * 2 + aSel) ^ l7) << 4);
                    ldsm_x4(addr, a[mf][0], a[mf][1], a[mf][2], a[mf][3]);
                }
#pragma unroll
                for (int p = 0; p < 4; p++) {
                    uint32_t b0a, b1a, b0b, b1b;
                    uint32_t addr = Bb + bCol[p] + ((uint32_t)((s * 2 + bSel) ^ l7) << 4);
                    ldsm_x4(addr, b0a, b1a, b0b, b1b);
                    mma_f16(acc[0][2 * p],     a[0][0], a[0][1], a[0][2], a[0][3], b0a, b1a);
                    mma_f16(acc[1][2 * p],     a[1][0], a[1][1], a[1][2], a[1][3], b0a, b1a);
                    mma_f16(acc[0][2 * p + 1], a[0][0], a[0][1], a[0][2], a[0][3], b0b, b1b);
                    mma_f16(acc[1][2 * p + 1], a[1][0], a[1][1], a[1][2], a[1][3], b0b, b1b);
                }
            }
            __syncthreads();
        }

        // fill next tile's chunk 1 during the epilogue (stage 1 free: chunk 7
        // computed + double-synced above)
        if (t_next < NTILES) {
            int rb = (t_next >> 5) * BM;
            int cb = (t_next & 31) * BN;
            load_chunk(g_srch, rb, KC, sbase + A_OFF(1));
            load_chunk(g_tgth, cb, KC, sbase + B_OFF(1));
            asm volatile("cp.async.commit_group;");
        }

        // ---- epilogue: dist -> clamp -> mask -> row max/min ----
#pragma unroll
        for (int mf = 0; mf < 2; mf++) {
#pragma unroll
            for (int half = 0; half < 2; half++) {
                int row = warpM * 32 + mf * 16 + half * 8 + gid;
                float e1v = sE1[row];
                int   lr  = sLr[row];
                float apv = 0.f;
                float anv = __int_as_float(0x7f800000);
#pragma unroll
                for (int nf = 0; nf < 8; nf++) {
                    int c0 = warpN * 64 + nf * 8 + t4 * 2;
#pragma unroll
                    for (int v = 0; v < 2; v++) {
                        int col = c0 + v;
                        float d = fmaf(-2.f, acc[mf][nf][half * 2 + v], e1v + sE2[col]);
                        d = fmaxf(d, 0.f);
                        if (lr == sLc[col]) apv = fmaxf(apv, d);
                        else                anv = fminf(anv, d);
                    }
                }
#pragma unroll
                for (int o = 1; o <= 2; o <<= 1) {
                    apv = fmaxf(apv, __shfl_xor_sync(0xffffffffu, apv, o));
                    anv = fminf(anv, __shfl_xor_sync(0xffffffffu, anv, o));
                }
                if (t4 == 0) {
                    atomicMax(&sAp[row], __float_as_uint(apv));
                    atomicMin(&sAn[row], __float_as_uint(anv));
                }
            }
        }
        __syncthreads();
        if (tid < 128) {
            atomicMax(&g_ap[rowBase + tid], sAp[tid]);
            atomicMin(&g_an[rowBase + tid], sAn[tid]);
        }

        if (t_next >= NTILES) break;

        // ---- advance to next tile ----
        t = t_next;
        rowBase = (t >> 5) * BM;
        colBase = (t & 31) * BN;
        __syncthreads();   // global atomics above done reading sAp/sAn
        if (tid < 128) {
            sAp[tid] = 0u;
            sAn[tid] = 0x7f800000u;
            sE1[tid] = g_e1[rowBase + tid];
            sE2[tid] = g_e2[colBase + tid];
            sLr[tid] = g_lab[rowBase + tid];
            sLc[tid] = g_lab[colBase + tid];
        }
#pragma unroll
        for (int mf = 0; mf < 2; mf++)
#pragma unroll
            for (int nf = 0; nf < 8; nf++)
#pragma unroll
                for (int v = 0; v < 4; v++) acc[mf][nf][v] = 0.f;
        // chunk 0 (in flight since c==7) and chunk 1 (just issued) pending;
        // loop iteration c=0 commits chunk 1's... (chunk1 already committed)
        // c=0 fills chunk 1? No: c=0 fills chunk 0+1=1 — already filled.
        // To keep the loop body uniform, chunk 1's fill above replaces the
        // c==0 fill; skip duplicate by advancing: handled below.
        t_next = NTILES;
        // NOTE: the inner loop's c==0 iteration would refill chunk 1; that
        // is redundant but harmless (same data, same stage, before wait).
    }
}

// ---------------------------------------------------------------------------
// reduce: deterministic single-block mean; one uint4 load round per array
// ---------------------------------------------------------------------------
__global__ void reduce_kernel(float* __restrict__ out) {
    __shared__ float sw[32];
    int t = threadIdx.x;  // 1024; thread t owns rows 4t..4t+3
    uint4 ap4 = *(const uint4*)&g_ap[t * 4];
    uint4 an4 = *(const uint4*)&g_an[t * 4];
    float s = fmaxf(__uint_as_float(ap4.x) - __uint_as_float(an4.x) + MARGIN_F, 0.f)
            + fmaxf(__uint_as_float(ap4.y) - __uint_as_float(an4.y) + MARGIN_F, 0.f)
            + fmaxf(__uint_as_float(ap4.z) - __uint_as_float(an4.z) + MARGIN_F, 0.f)
            + fmaxf(__uint_as_float(ap4.w) - __uint_as_float(an4.w) + MARGIN_F, 0.f);
#pragma unroll
    for (int o = 16; o > 0; o >>= 1) s += __shfl_xor_sync(0xffffffffu, s, o);
    if ((t & 31) == 0) sw[t >> 5] = s;
    __syncthreads();
    if (t < 32) {
        float v = sw[t];
#pragma unroll
        for (int o = 16; o > 0; o >>= 1) v += __shfl_xor_sync(0xffffffffu, v, o);
        if (t == 0) out[0] = v * (1.0f / (float)NN);
    }
}

// ---------------------------------------------------------------------------
extern "C" void kernel_launch(void* const* d_in, const int* in_sizes, int n_in,
                              void* d_out, int out_size) {
    const float* src = (const float*)d_in[0];
    const float* tgt = (const float*)d_in[1];
    const int*   lab = (const int*)d_in[2];

    cudaFuncSetAttribute(dist_mma_kernel,
                         cudaFuncAttributeMaxDynamicSharedMemorySize, DYN_SMEM);
    int sms = 148;
    cudaDeviceGetAttribute(&sms, cudaDevAttrMultiProcessorCount, 0);

    prep_kernel<<<NN / 4, 256>>>(src, tgt, lab);
    dist_mma_kernel<<<2 * sms, 256, DYN_SMEM>>>();
    reduce_kernel<<<1, 1024>>>((float*)d_out);
}

// round 14
// speedup vs baseline: 1.9721x; 1.9721x over previous
#include <cuda_runtime.h>
#include <cuda_fp16.h>
#include <cstdint>

#define NN 4096
#define DD 512
#define BM 128
#define BN 128
#define KC 64                    // fp16 K elems per chunk = 128B per row
#define NCHUNK (DD / KC)         // 8
#define MARGIN_F 0.3f

#define TILE_BYTES (BM * 128)    // 16 KB per operand per stage
#define A_OFF(s) ((s) * TILE_BYTES)
#define B_OFF(s) (2 * TILE_BYTES + (s) * TILE_BYTES)
#define DYN_SMEM (4 * TILE_BYTES)   // 64 KB (2-stage double buffer)

__device__ float    g_e1[NN];
__device__ float    g_e2[NN];
__device__ unsigned g_ap[NN];      // non-negative float bits, atomicMax
__device__ unsigned g_an[NN];      // non-negative float bits, atomicMin
__device__ int      g_lab[NN];
__device__ __half   g_srch[NN * DD];   // fp16 copies (4 MB each)
__device__ __half   g_tgth[NN * DD];

// ---------------------------------------------------------------------------
__device__ __forceinline__ uint32_t h2_bits(__half2 h) {
    return *reinterpret_cast<uint32_t*>(&h);
}
__device__ __forceinline__ uint32_t smem_u32(const void* p) {
    uint32_t a;
    asm("{ .reg .u64 t; cvta.to.shared.u64 t, %1; cvt.u32.u64 %0, t; }"
        : "=r"(a) : "l"(p));
    return a;
}
__device__ __forceinline__ void cp_async16(uint32_t dst, const void* src) {
    asm volatile("cp.async.cg.shared.global [%0], [%1], 16;" :: "r"(dst), "l"(src));
}
__device__ __forceinline__ void ldsm_x4(uint32_t addr, uint32_t& r0, uint32_t& r1,
                                        uint32_t& r2, uint32_t& r3) {
    asm volatile("ldmatrix.sync.aligned.m8n8.x4.shared.b16 {%0,%1,%2,%3}, [%4];"
                 : "=r"(r0), "=r"(r1), "=r"(r2), "=r"(r3) : "r"(addr));
}
__device__ __forceinline__ void mma_f16(float* d, uint32_t a0, uint32_t a1,
                                        uint32_t a2, uint32_t a3,
                                        uint32_t b0, uint32_t b1) {
    asm volatile(
        "mma.sync.aligned.m16n8k16.row.col.f32.f16.f16.f32 "
        "{%0,%1,%2,%3}, {%4,%5,%6,%7}, {%8,%9}, {%0,%1,%2,%3};"
        : "+f"(d[0]), "+f"(d[1]), "+f"(d[2]), "+f"(d[3])
        : "r"(a0), "r"(a1), "r"(a2), "r"(a3), "r"(b0), "r"(b1));
}

// ---------------------------------------------------------------------------
// prep: warp-per-(row, array). 1024 blocks x 256 threads = 8192 warps:
// warp slot s -> row = s>>1, array = s&1 (0=src, 1=tgt).
// fp16 stores via __stcg (dist consumes them from L2 via cp.async).
// Block 0 additionally: label dtype detect + normalize.
// ---------------------------------------------------------------------------
__global__ void __launch_bounds__(256) prep_kernel(const float* __restrict__ src,
                                                   const float* __restrict__ tgt,
                                                   const int* __restrict__ lab32) {
    const int wid = threadIdx.x >> 5;
    const int lid = threadIdx.x & 31;
    const int slot = blockIdx.x * 8 + wid;
    const int row = slot >> 1;
    const int arr = slot & 1;

    const float* base = arr ? tgt : src;
    __half* dsth = arr ? g_tgth : g_srch;

    const float4* s4 = (const float4*)(base + (size_t)row * DD);
    uint2* oh = (uint2*)(dsth + (size_t)row * DD);

    float4 xs[4];
#pragma unroll
    for (int i = 0; i < 4; i++) xs[i] = s4[lid + 32 * i];

    float a = 0.f;
#pragma unroll
    for (int i = 0; i < 4; i++) {
        float4 x = xs[i];
        a = fmaf(x.x, x.x, a); a = fmaf(x.y, x.y, a);
        a = fmaf(x.z, x.z, a); a = fmaf(x.w, x.w, a);
        uint2 o;
        o.x = h2_bits(__floats2half2_rn(x.x, x.y));
        o.y = h2_bits(__floats2half2_rn(x.z, x.w));
        __stcg(&oh[lid + 32 * i], o);
    }
#pragma unroll
    for (int o = 16; o > 0; o >>= 1)
        a += __shfl_xor_sync(0xffffffffu, a, o);
    if (lid == 0) {
        if (arr == 0) {
            g_e1[row] = a;
            g_ap[row] = 0u;
            g_an[row] = 0x7f800000u;
        } else {
            g_e2[row] = a;
        }
    }

    // ---- block 0 extra duty: labels (global dtype detection) ----
    if (blockIdx.x == 0) {
        __shared__ int any_odd_nonzero;
        const int t = threadIdx.x;
        if (t == 0) any_odd_nonzero = 0;
        __syncthreads();
        int local = 0;
        for (int i = 2 * t + 1; i < NN; i += 2 * 256)
            if (lab32[i] != 0) local = 1;
        if (local) atomicOr(&any_odd_nonzero, 1);
        __syncthreads();
        bool is64 = (any_odd_nonzero == 0);
        for (int i = t; i < NN; i += 256)
            g_lab[i] = is64 ? lab32[2 * i] : lab32[i];
    }
}

// ---------------------------------------------------------------------------
// dist_mma: UNCHANGED from best measured (R7/R11/R12): 128x128 tile, fp16
// m16n8k16, ldmatrix fragment feed, 2-stage cp.async double buffer with
// loads issued before the wait, fused label-masked row max/min epilogue.
// 8 warps: 4 (M) x 2 (N); warp tile 32x64.  DO NOT RESTRUCTURE (R8/R13
// regressions both came from touching this loop).
// ---------------------------------------------------------------------------
__global__ void __launch_bounds__(256, 2) dist_mma_kernel() {
    extern __shared__ char smem[];
    __shared__ float sE1[BM], sE2[BN];
    __shared__ int   sLr[BM], sLc[BN];
    __shared__ unsigned sAp[BM], sAn[BM];

    const int tid = threadIdx.x;
    const int wid = tid >> 5;
    const int lid = tid & 31;
    const int gid = lid >> 2;
    const int t4  = lid & 3;
    const int warpM = wid & 3;
    const int warpN = wid >> 2;
    const int rowBase = blockIdx.y * BM;
    const int colBase = blockIdx.x * BN;

    if (tid < 128) {
        sAp[tid] = 0u;
        sAn[tid] = 0x7f800000u;
        sE1[tid] = g_e1[rowBase + tid];
        sE2[tid] = g_e2[colBase + tid];
        sLr[tid] = g_lab[rowBase + tid];
        sLc[tid] = g_lab[colBase + tid];
    }

    const uint32_t sbase = smem_u32(smem);
    const int l7 = lid & 7;
    uint32_t aRow[2];
#pragma unroll
    for (int mf = 0; mf < 2; mf++)
        aRow[mf] = (uint32_t)((warpM * 32 + mf * 16 + ((lid >> 3) & 1) * 8 + l7) * 128);
    const int aSel = lid >> 4;
    uint32_t bCol[4];
#pragma unroll
    for (int p = 0; p < 4; p++)
        bCol[p] = (uint32_t)((warpN * 64 + p * 16 + (lid >> 4) * 8 + l7) * 128);
    const int bSel = (lid >> 3) & 1;

    // chunk loader: 128 rows x 128B (= 64 fp16), SW128 swizzle
    auto load_chunk = [&](const __half* __restrict__ base, int rb, int kt, uint32_t dst) {
#pragma unroll
        for (int i = 0; i < 4; i++) {
            int f = tid + i * 256;
            int r = f >> 3;
            int c16 = f & 7;
            const __half* g = base + (size_t)(rb + r) * DD + kt + c16 * 8;
            cp_async16(dst + r * 128 + ((c16 ^ (r & 7)) << 4), g);
        }
    };

    float acc[2][8][4];
#pragma unroll
    for (int mf = 0; mf < 2; mf++)
#pragma unroll
        for (int nf = 0; nf < 8; nf++)
#pragma unroll
            for (int v = 0; v < 4; v++) acc[mf][nf][v] = 0.f;

    load_chunk(g_srch, rowBase, 0, sbase + A_OFF(0));
    load_chunk(g_tgth, colBase, 0, sbase + B_OFF(0));
    asm volatile("cp.async.commit_group;");

    for (int c = 0; c < NCHUNK; c++) {
        int st = c & 1;
        if (c + 1 < NCHUNK) {
            int sn = (c + 1) & 1;
            load_chunk(g_srch, rowBase, (c + 1) * KC, sbase + A_OFF(sn));
            load_chunk(g_tgth, colBase, (c + 1) * KC, sbase + B_OFF(sn));
            asm volatile("cp.async.commit_group;");
            asm volatile("cp.async.wait_group 1;");
        } else {
            asm volatile("cp.async.wait_group 0;");
        }
        __syncthreads();

        const uint32_t Ab = sbase + A_OFF(st);
        const uint32_t Bb = sbase + B_OFF(st);
#pragma unroll
        for (int s = 0; s < 4; s++) {          // 4 x K=16
            uint32_t a[2][4];
#pragma unroll
            for (int mf = 0; mf < 2; mf++) {
                uint32_t addr = Ab + aRow[mf] + ((uint32_t)((s * 2 + aSel) ^ l7) << 4);
                ldsm_x4(addr, a[mf][0], a[mf][1], a[mf][2], a[mf][3]);
            }
#pragma unroll
            for (int p = 0; p < 4; p++) {
                uint32_t b0a, b1a, b0b, b1b;
                uint32_t addr = Bb + bCol[p] + ((uint32_t)((s * 2 + bSel) ^ l7) << 4);
                ldsm_x4(addr, b0a, b1a, b0b, b1b);
                mma_f16(acc[0][2 * p],     a[0][0], a[0][1], a[0][2], a[0][3], b0a, b1a);
                mma_f16(acc[1][2 * p],     a[1][0], a[1][1], a[1][2], a[1][3], b0a, b1a);
                mma_f16(acc[0][2 * p + 1], a[0][0], a[0][1], a[0][2], a[0][3], b0b, b1b);
                mma_f16(acc[1][2 * p + 1], a[1][0], a[1][1], a[1][2], a[1][3], b0b, b1b);
            }
        }
        __syncthreads();
    }

    // ---- epilogue: dist -> clamp -> mask -> row max/min ----
#pragma unroll
    for (int mf = 0; mf < 2; mf++) {
#pragma unroll
        for (int half = 0; half < 2; half++) {
            int row = warpM * 32 + mf * 16 + half * 8 + gid;
            float e1v = sE1[row];
            int   lr  = sLr[row];
            float apv = 0.f;
            float anv = __int_as_float(0x7f800000);
#pragma unroll
            for (int nf = 0; nf < 8; nf++) {
                int c0 = warpN * 64 + nf * 8 + t4 * 2;
#pragma unroll
                for (int v = 0; v < 2; v++) {
                    int col = c0 + v;
                    float d = fmaf(-2.f, acc[mf][nf][half * 2 + v], e1v + sE2[col]);
                    d = fmaxf(d, 0.f);
                    if (lr == sLc[col]) apv = fmaxf(apv, d);
                    else                anv = fminf(anv, d);
                }
            }
#pragma unroll
            for (int o = 1; o <= 2; o <<= 1) {
                apv = fmaxf(apv, __shfl_xor_sync(0xffffffffu, apv, o));
                anv = fminf(anv, __shfl_xor_sync(0xffffffffu, anv, o));
            }
            if (t4 == 0) {
                atomicMax(&sAp[row], __float_as_uint(apv));
                atomicMin(&sAn[row], __float_as_uint(anv));
            }
        }
    }
    __syncthreads();
    if (tid < 128) {
        atomicMax(&g_ap[rowBase + tid], sAp[tid]);
        atomicMin(&g_an[rowBase + tid], sAn[tid]);
    }
}

// ---------------------------------------------------------------------------
// reduce: deterministic single-block mean; 512 threads, 8 rows/thread,
// two independent uint4 load pairs (MLP=4)
// ---------------------------------------------------------------------------
__global__ void __launch_bounds__(512) reduce_kernel(float* __restrict__ out) {
    __shared__ float sw[16];
    int t = threadIdx.x;  // 512; thread t owns rows 8t..8t+7
    uint4 ap0 = *(const uint4*)&g_ap[t * 8];
    uint4 an0 = *(const uint4*)&g_an[t * 8];
    uint4 ap1 = *(const uint4*)&g_ap[t * 8 + 4];
    uint4 an1 = *(const uint4*)&g_an[t * 8 + 4];
    float s = fmaxf(__uint_as_float(ap0.x) - __uint_as_float(an0.x) + MARGIN_F, 0.f)
            + fmaxf(__uint_as_float(ap0.y) - __uint_as_float(an0.y) + MARGIN_F, 0.f)
            + fmaxf(__uint_as_float(ap0.z) - __uint_as_float(an0.z) + MARGIN_F, 0.f)
            + fmaxf(__uint_as_float(ap0.w) - __uint_as_float(an0.w) + MARGIN_F, 0.f)
            + fmaxf(__uint_as_float(ap1.x) - __uint_as_float(an1.x) + MARGIN_F, 0.f)
            + fmaxf(__uint_as_float(ap1.y) - __uint_as_float(an1.y) + MARGIN_F, 0.f)
            + fmaxf(__uint_as_float(ap1.z) - __uint_as_float(an1.z) + MARGIN_F, 0.f)
            + fmaxf(__uint_as_float(ap1.w) - __uint_as_float(an1.w) + MARGIN_F, 0.f);
#pragma unroll
    for (int o = 16; o > 0; o >>= 1) s += __shfl_xor_sync(0xffffffffu, s, o);
    if ((t & 31) == 0) sw[t >> 5] = s;
    __syncthreads();
    if (t < 16) {
        float v = sw[t];
#pragma unroll
        for (int o = 8; o > 0; o >>= 1) v += __shfl_xor_sync(0xffffu, v, o);
        if (t == 0) out[0] = v * (1.0f / (float)NN);
    }
}

// ---------------------------------------------------------------------------
extern "C" void kernel_launch(void* const* d_in, const int* in_sizes, int n_in,
                              void* d_out, int out_size) {
    const float* src = (const float*)d_in[0];
    const float* tgt = (const float*)d_in[1];
    const int*   lab = (const int*)d_in[2];

    cudaFuncSetAttribute(dist_mma_kernel,
                         cudaFuncAttributeMaxDynamicSharedMemorySize, DYN_SMEM);

    prep_kernel<<<NN / 4, 256>>>(src, tgt, lab);
    dist_mma_kernel<<<dim3(NN / BN, NN / BM), 256, DYN_SMEM>>>();
    reduce_kernel<<<1, 512>>>((float*)d_out);
}